// round 5
// baseline (speedup 1.0000x reference)
#include <cuda_runtime.h>
#include <math.h>

#define DN 512
#define BN 256
#define TN 300

// ---------------- scratch (static device globals; no runtime allocation) ----------------
__device__ float g_A[(size_t)BN * DN * DN];          // per-batch working matrix (reversed prec -> L')
__device__ float g_Dinv[(size_t)BN * 8 * 64 * 64];   // per-batch diag-block inverses of L'
__device__ float g_M[DN * DN];                       // inv(chol_w) * diag(exp(-Dw/2)), upper
__device__ float g_Prev[DN * DN];                    // P with both indices reversed
__device__ float g_gamma[BN * DN];                   // weighted first-order stats
__device__ float g_Ns[BN];                           // sum of weights per batch

// ---------------- 1) gamma[b,d] = sum_t x*w ; N[b] = sum_t w ----------------
__global__ void stats_kernel(const float* __restrict__ x, const float* __restrict__ w) {
    __shared__ float sw[TN];
    __shared__ float red[512];
    int b = blockIdx.x, tid = threadIdx.x;
    const float* wb = w + b * TN;
    float ws = 0.f;
    for (int t = tid; t < TN; t += 512) { float v = wb[t]; sw[t] = v; ws += v; }
    red[tid] = ws;
    __syncthreads();
    for (int s = 256; s > 0; s >>= 1) { if (tid < s) red[tid] += red[tid + s]; __syncthreads(); }
    if (tid == 0) g_Ns[b] = red[0];
    const float* xb = x + (size_t)b * TN * DN;
    float acc = 0.f;
    for (int t = 0; t < TN; t++) acc += xb[(size_t)t * DN + tid] * sw[t];
    g_gamma[b * DN + tid] = acc;
}

// ---------------- 2) M = inv(chol_w) (upper) with column k scaled by exp(-Dw[k]/2) ----------------
// one warp per column: back-substitution  U c = e_j
__global__ void trinvU_kernel(const float* __restrict__ U, const float* __restrict__ Dw) {
    __shared__ float sc[8][DN];
    int wrp = threadIdx.x >> 5, lane = threadIdx.x & 31;
    int j = blockIdx.x * 8 + wrp;
    float* c = sc[wrp];
    float sj = expf(-0.5f * Dw[j]);
    if (lane == 0) c[j] = 1.0f / U[(size_t)j * DN + j];
    __syncwarp();
    for (int i = j - 1; i >= 0; --i) {
        float p = 0.f;
        for (int k = i + 1 + lane; k <= j; k += 32) p += U[(size_t)i * DN + k] * c[k];
        #pragma unroll
        for (int o = 16; o; o >>= 1) p += __shfl_down_sync(0xffffffffu, p, o);
        if (lane == 0) c[i] = -p / U[(size_t)i * DN + i];
        __syncwarp();
    }
    for (int i = lane; i < DN; i += 32)
        g_M[(size_t)i * DN + j] = (i <= j) ? c[i] * sj : 0.f;
}

// ---------------- 3) Prev[i][j] = P[511-i][511-j],  P = M M^T ----------------
__global__ void formP_kernel() {
    __shared__ float sA[32][33], sB[32][33];
    int i0 = blockIdx.y * 32, j0 = blockIdx.x * 32;
    int lane = threadIdx.x & 31;
    int r4 = (threadIdx.x >> 5) * 4;
    float a0 = 0.f, a1 = 0.f, a2 = 0.f, a3 = 0.f;
    for (int k0 = 0; k0 < DN; k0 += 32) {
        for (int u = threadIdx.x; u < 32 * 32; u += 256) {
            int r = u >> 5, k = u & 31;
            sA[r][k] = g_M[(size_t)(DN - 1 - (i0 + r)) * DN + k0 + k];
            sB[r][k] = g_M[(size_t)(DN - 1 - (j0 + r)) * DN + k0 + k];
        }
        __syncthreads();
        #pragma unroll 8
        for (int k = 0; k < 32; k++) {
            float bv = sB[lane][k];
            a0 += sA[r4 + 0][k] * bv; a1 += sA[r4 + 1][k] * bv;
            a2 += sA[r4 + 2][k] * bv; a3 += sA[r4 + 3][k] * bv;
        }
        __syncthreads();
    }
    g_Prev[(size_t)(i0 + r4 + 0) * DN + j0 + lane] = a0;
    g_Prev[(size_t)(i0 + r4 + 1) * DN + j0 + lane] = a1;
    g_Prev[(size_t)(i0 + r4 + 2) * DN + j0 + lane] = a2;
    g_Prev[(size_t)(i0 + r4 + 3) * DN + j0 + lane] = a3;
}

// ---------------- 4) A_b = I + N_b * Prev ----------------
__global__ void initA_kernel() {
    int b = blockIdx.y;
    int e4 = blockIdx.x * blockDim.x + threadIdx.x;   // 0..65535 float4s
    float nb = g_Ns[b];
    float4 p = ((const float4*)g_Prev)[e4];
    int base = e4 << 2;
    int i = base >> 9, j = base & 511;
    float4 v;
    v.x = nb * p.x + (i == j     ? 1.f : 0.f);
    v.y = nb * p.y + (i == j + 1 ? 1.f : 0.f);
    v.z = nb * p.z + (i == j + 2 ? 1.f : 0.f);
    v.w = nb * p.w + (i == j + 3 ? 1.f : 0.f);
    ((float4*)(g_A + (size_t)b * DN * DN))[e4] = v;
}

// ---------------- 5) batched blocked Cholesky (lower) + save diag-block inverses ----------------
__global__ void potrf_kernel() {
    const int b = blockIdx.x;
    float* A = g_A + (size_t)b * DN * DN;
    float* Dv = g_Dinv + (size_t)b * 8 * 4096;
    extern __shared__ float sm[];
    float* sDiag = sm;               // 64*65
    float* sInv  = sm + 4160;
    float* sA    = sm + 8320;
    float* sB    = sm + 12480;
    int tid = threadIdx.x;
    int tx = tid & 15, ty = tid >> 4;

    for (int kb = 0; kb < 8; kb++) {
        int base = kb * 64;
        // load diag block
        for (int u = tid; u < 64 * 64; u += 256) {
            int r = u >> 6, c = u & 63;
            sDiag[r * 65 + c] = A[(size_t)(base + r) * DN + base + c];
        }
        __syncthreads();
        // unblocked Cholesky in SMEM (lower)
        for (int j = 0; j < 64; j++) {
            if (tid == 0) sDiag[j * 65 + j] = sqrtf(sDiag[j * 65 + j]);
            __syncthreads();
            float rinv = 1.0f / sDiag[j * 65 + j];
            for (int i = j + 1 + tid; i < 64; i += 256) sDiag[i * 65 + j] *= rinv;
            __syncthreads();
            for (int u = tid; u < 64 * 64; u += 256) {
                int i = u >> 6, c = u & 63;
                if (c > j && i >= c)
                    sDiag[i * 65 + c] -= sDiag[i * 65 + j] * sDiag[c * 65 + j];
            }
            __syncthreads();
        }
        // sInv = inv(L_kk), lower; zero first (keeps upper zero for full k-loops later)
        for (int u = tid; u < 64 * 65; u += 256) sInv[u] = 0.f;
        __syncthreads();
        if (tid < 64) {
            int c = tid;
            float x = 1.0f / sDiag[c * 65 + c];
            sInv[c * 65 + c] = x;
            for (int i = c + 1; i < 64; i++) {
                float s = 0.f;
                for (int k = c; k < i; k++) s += sDiag[i * 65 + k] * sInv[k * 65 + c];
                sInv[i * 65 + c] = -s / sDiag[i * 65 + i];
            }
        }
        __syncthreads();
        // write back L_kk and Dinv
        for (int u = tid; u < 64 * 64; u += 256) {
            int r = u >> 6, c = u & 63;
            A[(size_t)(base + r) * DN + base + c] = sDiag[r * 65 + c];
            Dv[kb * 4096 + u] = sInv[r * 65 + c];
        }
        __syncthreads();

        int nrem = DN - base - 64;
        // panel solve: L21 = A21 * inv(L_kk)^T
        for (int t = 0; t < nrem / 64; t++) {
            int r0 = base + 64 + t * 64;
            for (int u = tid; u < 64 * 64; u += 256) {
                int r = u >> 6, c = u & 63;
                sA[r * 65 + c] = A[(size_t)(r0 + r) * DN + base + c];
            }
            __syncthreads();
            float acc[4][4];
            #pragma unroll
            for (int a = 0; a < 4; a++)
                #pragma unroll
                for (int q = 0; q < 4; q++) acc[a][q] = 0.f;
            #pragma unroll 8
            for (int k = 0; k < 64; k++) {
                float av[4], bv[4];
                #pragma unroll
                for (int a = 0; a < 4; a++) av[a] = sA[(ty * 4 + a) * 65 + k];
                #pragma unroll
                for (int q = 0; q < 4; q++) bv[q] = sInv[(tx * 4 + q) * 65 + k];
                #pragma unroll
                for (int a = 0; a < 4; a++)
                    #pragma unroll
                    for (int q = 0; q < 4; q++) acc[a][q] += av[a] * bv[q];
            }
            __syncthreads();
            #pragma unroll
            for (int a = 0; a < 4; a++) {
                float4* p = (float4*)&A[(size_t)(r0 + ty * 4 + a) * DN + base + tx * 4];
                *p = make_float4(acc[a][0], acc[a][1], acc[a][2], acc[a][3]);
            }
        }
        __syncthreads();   // L21 global writes visible to SYRK loads below

        // SYRK: A22 -= L21 L21^T (lower tiles only)
        for (int Ib = kb + 1; Ib < 8; Ib++) {
            for (int Jb = kb + 1; Jb <= Ib; Jb++) {
                int rI = Ib * 64, rJ = Jb * 64;
                for (int u = tid; u < 64 * 64; u += 256) {
                    int r = u >> 6, c = u & 63;
                    sA[r * 65 + c] = A[(size_t)(rI + r) * DN + base + c];
                    sB[r * 65 + c] = A[(size_t)(rJ + r) * DN + base + c];
                }
                __syncthreads();
                float acc[4][4];
                #pragma unroll
                for (int a = 0; a < 4; a++)
                    #pragma unroll
                    for (int q = 0; q < 4; q++) acc[a][q] = 0.f;
                #pragma unroll 8
                for (int k = 0; k < 64; k++) {
                    float av[4], bv[4];
                    #pragma unroll
                    for (int a = 0; a < 4; a++) av[a] = sA[(ty * 4 + a) * 65 + k];
                    #pragma unroll
                    for (int q = 0; q < 4; q++) bv[q] = sB[(tx * 4 + q) * 65 + k];
                    #pragma unroll
                    for (int a = 0; a < 4; a++)
                        #pragma unroll
                        for (int q = 0; q < 4; q++) acc[a][q] += av[a] * bv[q];
                }
                __syncthreads();
                #pragma unroll
                for (int a = 0; a < 4; a++) {
                    float4* p = (float4*)&A[(size_t)(rI + ty * 4 + a) * DN + rJ + tx * 4];
                    float4 v = *p;
                    v.x -= acc[a][0]; v.y -= acc[a][1]; v.z -= acc[a][2]; v.w -= acc[a][3];
                    *p = v;
                }
            }
        }
        __syncthreads();
    }
}

// index map: W[r][c]  ->  chol[b][511-r][511-c]
// ---------------- 6) batched blocked lower-triangular inverse, written into chol region ----------------
__global__ void trinv_main_kernel(float* __restrict__ cholg) {
    int Jb = blockIdx.x, b = blockIdx.y;
    const float* A  = g_A + (size_t)b * DN * DN;
    const float* Dv = g_Dinv + (size_t)b * 8 * 4096;
    float* C = cholg + (size_t)b * DN * DN;
    extern __shared__ float sm[];
    float* sL = sm;           // 64*65
    float* sW = sm + 4160;
    float* sS = sm + 8320;
    float* sD = sm + 12480;
    int tid = threadIdx.x, tx = tid & 15, ty = tid >> 4;

    // W_JJ = Dinv_J
    for (int u = tid; u < 4096; u += 256) {
        int r = u >> 6, c = u & 63;
        C[(size_t)(DN - 1 - (Jb * 64 + r)) * DN + (DN - 1 - (Jb * 64 + c))] = Dv[Jb * 4096 + u];
    }
    __syncthreads();

    for (int Ib = Jb + 1; Ib < 8; Ib++) {
        float acc[4][4];
        #pragma unroll
        for (int a = 0; a < 4; a++)
            #pragma unroll
            for (int q = 0; q < 4; q++) acc[a][q] = 0.f;
        for (int Kb = Jb; Kb < Ib; Kb++) {
            for (int u = tid; u < 4096; u += 256) {
                int r = u >> 6, c = u & 63;
                sL[r * 65 + c] = A[(size_t)(Ib * 64 + r) * DN + Kb * 64 + c];
                sW[r * 65 + c] = (Kb == Jb)
                    ? Dv[Jb * 4096 + u]
                    : C[(size_t)(DN - 1 - (Kb * 64 + r)) * DN + (DN - 1 - (Jb * 64 + c))];
            }
            __syncthreads();
            #pragma unroll 8
            for (int k = 0; k < 64; k++) {
                float av[4], bv[4];
                #pragma unroll
                for (int a = 0; a < 4; a++) av[a] = sL[(ty * 4 + a) * 65 + k];
                #pragma unroll
                for (int q = 0; q < 4; q++) bv[q] = sW[k * 65 + tx * 4 + q];
                #pragma unroll
                for (int a = 0; a < 4; a++)
                    #pragma unroll
                    for (int q = 0; q < 4; q++) acc[a][q] += av[a] * bv[q];
            }
            __syncthreads();
        }
        // W_IJ = -Dinv_I * S
        #pragma unroll
        for (int a = 0; a < 4; a++)
            #pragma unroll
            for (int q = 0; q < 4; q++) sS[(ty * 4 + a) * 65 + tx * 4 + q] = acc[a][q];
        for (int u = tid; u < 4096; u += 256)
            sD[(u >> 6) * 65 + (u & 63)] = Dv[Ib * 4096 + u];
        __syncthreads();
        float wv[4][4];
        #pragma unroll
        for (int a = 0; a < 4; a++)
            #pragma unroll
            for (int q = 0; q < 4; q++) wv[a][q] = 0.f;
        #pragma unroll 8
        for (int k = 0; k < 64; k++) {
            float av[4], bv[4];
            #pragma unroll
            for (int a = 0; a < 4; a++) av[a] = sD[(ty * 4 + a) * 65 + k];
            #pragma unroll
            for (int q = 0; q < 4; q++) bv[q] = sS[k * 65 + tx * 4 + q];
            #pragma unroll
            for (int a = 0; a < 4; a++)
                #pragma unroll
                for (int q = 0; q < 4; q++) wv[a][q] += av[a] * bv[q];
        }
        #pragma unroll
        for (int a = 0; a < 4; a++)
            #pragma unroll
            for (int q = 0; q < 4; q++)
                C[(size_t)(DN - 1 - (Ib * 64 + ty * 4 + a)) * DN +
                  (DN - 1 - (Jb * 64 + tx * 4 + q))] = -wv[a][q];
        __syncthreads();
    }
}

// ---------------- 7) mu = J * (W^T (W * gamma_rev))  (uses UNNORMALIZED W in chol region) ----------------
__global__ void mu_kernel(const float* __restrict__ cholg, float* __restrict__ mu) {
    int b = blockIdx.x;
    const float* C = cholg + (size_t)b * DN * DN;
    __shared__ float sg[DN], st[DN], sp[8][DN];
    int tid = threadIdx.x, wrp = tid >> 5, lane = tid & 31;
    for (int i = tid; i < DN; i += 256) sg[i] = g_gamma[b * DN + (DN - 1 - i)];
    for (int j = lane; j < DN; j += 32) sp[wrp][j] = 0.f;
    __syncthreads();
    // t = W * g~   (W[i][j] = C[511-i][511-j], lower)
    for (int i = wrp; i < DN; i += 8) {
        float p = 0.f;
        for (int j = lane; j <= i; j += 32)
            p += C[(size_t)(DN - 1 - i) * DN + (DN - 1 - j)] * sg[j];
        #pragma unroll
        for (int o = 16; o; o >>= 1) p += __shfl_down_sync(0xffffffffu, p, o);
        if (lane == 0) st[i] = p;
    }
    __syncthreads();
    // mu~ = W^T t  via per-warp partial accumulators
    for (int i = wrp; i < DN; i += 8) {
        float ti = st[i];
        for (int j = lane; j <= i; j += 32)
            sp[wrp][j] += C[(size_t)(DN - 1 - i) * DN + (DN - 1 - j)] * ti;
    }
    __syncthreads();
    for (int j = tid; j < DN; j += 256) {
        float s = 0.f;
        #pragma unroll
        for (int w = 0; w < 8; w++) s += sp[w][j];
        mu[b * DN + (DN - 1 - j)] = s;
    }
}

// ---------------- 8) finalize: row-normalize chol, zero sub-diagonal, unit diag; logvar ----------------
__global__ void finalize_kernel(float* __restrict__ cholg, float* __restrict__ logvar) {
    int b = blockIdx.y;
    int e4 = blockIdx.x * blockDim.x + threadIdx.x;   // 0..65535
    int base = e4 << 2;
    int i = base >> 9, j0 = base & 511;
    int r = DN - 1 - i;
    float Ld = g_A[(size_t)b * DN * DN + (size_t)r * DN + r];   // L'[r][r]
    float4* p = (float4*)(cholg + (size_t)b * DN * DN) + e4;
    float4 v = *p;
    float vals[4] = {v.x, v.y, v.z, v.w};
    #pragma unroll
    for (int q = 0; q < 4; q++) {
        int j = j0 + q;
        vals[q] = (j < i) ? 0.f : ((j == i) ? 1.f : vals[q] * Ld);
    }
    *p = make_float4(vals[0], vals[1], vals[2], vals[3]);
    if (j0 == 0) logvar[b * DN + i] = -2.f * logf(Ld);
}

// ---------------- launch ----------------
extern "C" void kernel_launch(void* const* d_in, const int* in_sizes, int n_in,
                              void* d_out, int out_size) {
    const float* x     = (const float*)d_in[0];   // [B,T,D]
    const float* w     = (const float*)d_in[1];   // [B,T,1]
    const float* Dw    = (const float*)d_in[2];   // [D]
    const float* cholw = (const float*)d_in[3];   // [D,D]
    float* out    = (float*)d_out;
    float* mu     = out;                          // [B,D]
    float* logvar = out + BN * DN;                // [B,D]
    float* chol   = out + 2 * BN * DN;            // [B,D,D]

    const int SMEM = 4 * 64 * 65 * (int)sizeof(float);   // 66560 B
    cudaFuncSetAttribute((const void*)potrf_kernel,
                         cudaFuncAttributeMaxDynamicSharedMemorySize, SMEM);
    cudaFuncSetAttribute((const void*)trinv_main_kernel,
                         cudaFuncAttributeMaxDynamicSharedMemorySize, SMEM);

    stats_kernel<<<BN, 512>>>(x, w);
    trinvU_kernel<<<64, 256>>>(cholw, Dw);
    formP_kernel<<<dim3(16, 16), 256>>>();
    initA_kernel<<<dim3(256, BN), 256>>>();
    potrf_kernel<<<BN, 256, SMEM>>>();
    trinv_main_kernel<<<dim3(8, BN), 256, SMEM>>>(chol);
    mu_kernel<<<BN, 256>>>(chol, mu);
    finalize_kernel<<<dim3(256, BN), 256>>>(chol, logvar);
}

// round 11
// speedup vs baseline: 1.0230x; 1.0230x over previous
#include <cuda_runtime.h>
#include <math.h>

#define DN 512
#define BN 256
#define TN 300
#define PIT 68    // k-major smem pitch (mult of 4 for float4, 4-bank skew)
#define DPIT 65   // row-major diag pitch

// ---------------- scratch (static device globals; no runtime allocation) ----------------
__device__ float g_A[(size_t)BN * DN * DN];          // per-batch working matrix (reversed prec -> L')
__device__ float g_Dinv[(size_t)BN * 8 * 64 * 64];   // per-batch diag-block inverses (row-major Inv[r][c])
__device__ float g_M[DN * DN];                       // inv(chol_w) * diag(exp(-Dw/2)), upper
__device__ float g_Prev[DN * DN];                    // P with both indices reversed
__device__ float g_gamma[BN * DN];                   // weighted first-order stats
__device__ float g_Ns[BN];                           // sum of weights per batch

// ---------------- 1) gamma[b,d] = sum_t x*w ; N[b] = sum_t w ----------------
__global__ void stats_kernel(const float* __restrict__ x, const float* __restrict__ w) {
    __shared__ float sw[TN];
    __shared__ float red[512];
    int b = blockIdx.x, tid = threadIdx.x;
    const float* wb = w + b * TN;
    float ws = 0.f;
    for (int t = tid; t < TN; t += 512) { float v = wb[t]; sw[t] = v; ws += v; }
    red[tid] = ws;
    __syncthreads();
    for (int s = 256; s > 0; s >>= 1) { if (tid < s) red[tid] += red[tid + s]; __syncthreads(); }
    if (tid == 0) g_Ns[b] = red[0];
    const float* xb = x + (size_t)b * TN * DN;
    float acc = 0.f;
    for (int t = 0; t < TN; t++) acc += xb[(size_t)t * DN + tid] * sw[t];
    g_gamma[b * DN + tid] = acc;
}

// ---------------- 2) M = inv(chol_w) (upper) with column k scaled by exp(-Dw[k]/2) ----------------
__global__ void trinvU_kernel(const float* __restrict__ U, const float* __restrict__ Dw) {
    __shared__ float sc[8][DN];
    int wrp = threadIdx.x >> 5, lane = threadIdx.x & 31;
    int j = blockIdx.x * 8 + wrp;
    float* c = sc[wrp];
    float sj = expf(-0.5f * Dw[j]);
    if (lane == 0) c[j] = 1.0f / U[(size_t)j * DN + j];
    __syncwarp();
    for (int i = j - 1; i >= 0; --i) {
        float p = 0.f;
        for (int k = i + 1 + lane; k <= j; k += 32) p += U[(size_t)i * DN + k] * c[k];
        #pragma unroll
        for (int o = 16; o; o >>= 1) p += __shfl_down_sync(0xffffffffu, p, o);
        if (lane == 0) c[i] = -p / U[(size_t)i * DN + i];
        __syncwarp();
    }
    for (int i = lane; i < DN; i += 32)
        g_M[(size_t)i * DN + j] = (i <= j) ? c[i] * sj : 0.f;
}

// ---------------- 3) Prev[i][j] = P[511-i][511-j],  P = M M^T ----------------
__global__ void formP_kernel() {
    __shared__ float sA[32][33], sB[32][33];
    int i0 = blockIdx.y * 32, j0 = blockIdx.x * 32;
    int lane = threadIdx.x & 31;
    int r4 = (threadIdx.x >> 5) * 4;
    float a0 = 0.f, a1 = 0.f, a2 = 0.f, a3 = 0.f;
    for (int k0 = 0; k0 < DN; k0 += 32) {
        for (int u = threadIdx.x; u < 32 * 32; u += 256) {
            int r = u >> 5, k = u & 31;
            sA[r][k] = g_M[(size_t)(DN - 1 - (i0 + r)) * DN + k0 + k];
            sB[r][k] = g_M[(size_t)(DN - 1 - (j0 + r)) * DN + k0 + k];
        }
        __syncthreads();
        #pragma unroll 8
        for (int k = 0; k < 32; k++) {
            float bv = sB[lane][k];
            a0 += sA[r4 + 0][k] * bv; a1 += sA[r4 + 1][k] * bv;
            a2 += sA[r4 + 2][k] * bv; a3 += sA[r4 + 3][k] * bv;
        }
        __syncthreads();
    }
    g_Prev[(size_t)(i0 + r4 + 0) * DN + j0 + lane] = a0;
    g_Prev[(size_t)(i0 + r4 + 1) * DN + j0 + lane] = a1;
    g_Prev[(size_t)(i0 + r4 + 2) * DN + j0 + lane] = a2;
    g_Prev[(size_t)(i0 + r4 + 3) * DN + j0 + lane] = a3;
}

// ---------------- 4) init block-column 0 only: A[:,0:64] = I + N_b * Prev[:,0:64] ----------------
__global__ void initA_kernel() {
    int b = blockIdx.y;
    int e4 = blockIdx.x * blockDim.x + threadIdx.x;   // 0..8191
    float nb = g_Ns[b];
    int base = e4 << 2;
    int i = base >> 6;     // row 0..511
    int j = base & 63;     // col 0..63
    float4 p = *(const float4*)(g_Prev + (size_t)i * DN + j);
    float4 v;
    v.x = nb * p.x + (float)(i == j);
    v.y = nb * p.y + (float)(i == j + 1);
    v.z = nb * p.z + (float)(i == j + 2);
    v.w = nb * p.w + (float)(i == j + 3);
    *(float4*)(g_A + (size_t)b * DN * DN + (size_t)i * DN + j) = v;
}

// ---- load 64x64 tile (row r, col k at g[r*ld+k]) transposed into sT[k*PIT + r] ----
__device__ __forceinline__ void load_tile_T(const float* __restrict__ g, int ld,
                                            float* sT, int tid) {
    for (int u4 = tid; u4 < 1024; u4 += 256) {
        int r = u4 >> 4, k4 = (u4 & 15) << 2;
        float4 v = *(const float4*)(g + (size_t)r * ld + k4);
        sT[(k4 + 0) * PIT + r] = v.x;
        sT[(k4 + 1) * PIT + r] = v.y;
        sT[(k4 + 2) * PIT + r] = v.z;
        sT[(k4 + 3) * PIT + r] = v.w;
    }
}

// ---- C[r][c] += sum_k A[r][k]*B[c][k]; operands k-major: sA[k][r], sB[k][c] ----
__device__ __forceinline__ void gemm64(const float* __restrict__ sA, const float* __restrict__ sB,
                                       float acc[4][4], int tx, int ty) {
    #pragma unroll 8
    for (int k = 0; k < 64; k++) {
        float4 a4 = *(const float4*)(sA + k * PIT + (ty << 2));
        float4 b4 = *(const float4*)(sB + k * PIT + (tx << 2));
        acc[0][0] += a4.x * b4.x; acc[0][1] += a4.x * b4.y; acc[0][2] += a4.x * b4.z; acc[0][3] += a4.x * b4.w;
        acc[1][0] += a4.y * b4.x; acc[1][1] += a4.y * b4.y; acc[1][2] += a4.y * b4.z; acc[1][3] += a4.y * b4.w;
        acc[2][0] += a4.z * b4.x; acc[2][1] += a4.z * b4.y; acc[2][2] += a4.z * b4.z; acc[2][3] += a4.z * b4.w;
        acc[3][0] += a4.w * b4.x; acc[3][1] += a4.w * b4.y; acc[3][2] += a4.w * b4.z; acc[3][3] += a4.w * b4.w;
    }
}

// ---------------- 5) batched blocked Cholesky + diag-block inverses ----------------
__global__ void __launch_bounds__(256, 2) potrf_kernel() {
    const int b = blockIdx.x;
    float* A = g_A + (size_t)b * DN * DN;
    float* Dv = g_Dinv + (size_t)b * 8 * 4096;
    const float nb = g_Ns[b];
    extern __shared__ float sm[];
    float* sDiag = sm;            // 64*65
    float* sIT   = sm + 4160;     // 64*68 : sIT[k*PIT+c] = Inv[c][k]
    float* sTa   = sm + 8512;     // 64*68
    float* sTb   = sm + 12864;    // 64*68
    int tid = threadIdx.x, tx = tid & 15, ty = tid >> 4;

    for (int kb = 0; kb < 8; kb++) {
        int base = kb * 64;
        // load diag block (row-major)
        for (int u4 = tid; u4 < 1024; u4 += 256) {
            int r = u4 >> 4, c4 = (u4 & 15) << 2;
            float4 v = *(const float4*)(A + (size_t)(base + r) * DN + base + c4);
            sDiag[r * DPIT + c4 + 0] = v.x; sDiag[r * DPIT + c4 + 1] = v.y;
            sDiag[r * DPIT + c4 + 2] = v.z; sDiag[r * DPIT + c4 + 3] = v.w;
        }
        __syncthreads();
        // unblocked Cholesky (lower)
        for (int j = 0; j < 64; j++) {
            if (tid == 0) sDiag[j * DPIT + j] = sqrtf(sDiag[j * DPIT + j]);
            __syncthreads();
            float rinv = 1.0f / sDiag[j * DPIT + j];
            for (int i = j + 1 + tid; i < 64; i += 256) sDiag[i * DPIT + j] *= rinv;
            __syncthreads();
            for (int u = tid; u < 4096; u += 256) {
                int i = u >> 6, c = u & 63;
                if (c > j && i >= c)
                    sDiag[i * DPIT + c] -= sDiag[i * DPIT + j] * sDiag[c * DPIT + j];
            }
            __syncthreads();
        }
        // inv(L_kk) into k-major sIT (zero first)
        for (int u = tid; u < 64 * PIT; u += 256) sIT[u] = 0.f;
        __syncthreads();
        if (tid < 64) {
            int c = tid;
            float x = 1.0f / sDiag[c * DPIT + c];
            sIT[c * PIT + c] = x;
            for (int i = c + 1; i < 64; i++) {
                float s = 0.f;
                for (int k = c; k < i; k++) s += sDiag[i * DPIT + k] * sIT[c * PIT + k];
                sIT[c * PIT + i] = -s / sDiag[i * DPIT + i];
            }
        }
        __syncthreads();
        // writeback L_kk and Dv (plain row-major Inv[r][c])
        for (int u = tid; u < 4096; u += 256) {
            int r = u >> 6, c = u & 63;
            A[(size_t)(base + r) * DN + base + c] = sDiag[r * DPIT + c];
            Dv[kb * 4096 + u] = sIT[c * PIT + r];
        }
        __syncthreads();

        int ntiles = 7 - kb;
        // panel solve: L21 = A21 * inv(L_kk)^T
        for (int t = 0; t < ntiles; t++) {
            int r0 = base + 64 + t * 64;
            load_tile_T(A + (size_t)r0 * DN + base, DN, sTa, tid);
            __syncthreads();
            float acc[4][4] = {};
            gemm64(sTa, sIT, acc, tx, ty);
            __syncthreads();
            #pragma unroll
            for (int a = 0; a < 4; a++)
                *(float4*)(A + (size_t)(r0 + (ty << 2) + a) * DN + base + (tx << 2)) =
                    make_float4(acc[a][0], acc[a][1], acc[a][2], acc[a][3]);
        }
        __syncthreads();

        // SYRK: A22 -= L21 L21^T ; at kb==0 fuse init: A22 = I + nb*Prev - acc
        for (int Ib = kb + 1; Ib < 8; Ib++) {
            for (int Jb = kb + 1; Jb <= Ib; Jb++) {
                int rI = Ib * 64, rJ = Jb * 64;
                load_tile_T(A + (size_t)rI * DN + base, DN, sTa, tid);
                load_tile_T(A + (size_t)rJ * DN + base, DN, sTb, tid);
                __syncthreads();
                float acc[4][4] = {};
                gemm64(sTa, sTb, acc, tx, ty);
                __syncthreads();
                if (kb == 0) {
                    #pragma unroll
                    for (int a = 0; a < 4; a++) {
                        int gr = rI + (ty << 2) + a, gc0 = rJ + (tx << 2);
                        float4 p = *(const float4*)(g_Prev + (size_t)gr * DN + gc0);
                        float4 v;
                        v.x = nb * p.x + (float)(gr == gc0)     - acc[a][0];
                        v.y = nb * p.y + (float)(gr == gc0 + 1) - acc[a][1];
                        v.z = nb * p.z + (float)(gr == gc0 + 2) - acc[a][2];
                        v.w = nb * p.w + (float)(gr == gc0 + 3) - acc[a][3];
                        *(float4*)(A + (size_t)gr * DN + gc0) = v;
                    }
                } else {
                    #pragma unroll
                    for (int a = 0; a < 4; a++) {
                        float4* p = (float4*)(A + (size_t)(rI + (ty << 2) + a) * DN + rJ + (tx << 2));
                        float4 v = *p;
                        v.x -= acc[a][0]; v.y -= acc[a][1]; v.z -= acc[a][2]; v.w -= acc[a][3];
                        *p = v;
                    }
                }
            }
        }
        __syncthreads();
    }
}

// index map: W[r][c] -> chol[b][511-r][511-c], stored NORMALIZED: C = W[r][c]*dL[r] (r>c), 1 (r==c), 0 else
// ---------------- 6) batched blocked triangular inverse, normalized output in place ----------------
__global__ void __launch_bounds__(256, 2) trinv_main_kernel(float* __restrict__ cholg) {
    int Jb = blockIdx.x, b = blockIdx.y;
    const float* A  = g_A + (size_t)b * DN * DN;
    const float* Dv = g_Dinv + (size_t)b * 8 * 4096;
    float* C = cholg + (size_t)b * DN * DN;
    extern __shared__ float sm[];
    float* sL  = sm;              // 64*68
    float* sW  = sm + 4352;       // 64*68 (natural [k][c])
    float* sS  = sm + 8704;       // 64*68
    float* sD  = sm + 13056;      // 64*68
    float* sdl = sm + 17408;      // 512 diag of L'
    float* srl = sm + 17920;      // 512 reciprocal diag
    int tid = threadIdx.x, tx = tid & 15, ty = tid >> 4;
    int J64 = Jb * 64;

    for (int i = tid; i < DN; i += 256) {
        float d = A[(size_t)i * DN + i];
        sdl[i] = d; srl[i] = 1.0f / d;
    }
    __syncthreads();

    // diagonal output block: unit diag, zeros above (in W coords), scaled below
    for (int u = tid; u < 4096; u += 256) {
        int r = u >> 6, c = u & 63;
        float v = Dv[Jb * 4096 + u];
        float outv = (r > c) ? v * sdl[J64 + r] : ((r == c) ? 1.f : 0.f);
        C[(size_t)(DN - 1 - (J64 + r)) * DN + (DN - 1 - (J64 + c))] = outv;
    }

    for (int Ib = Jb + 1; Ib < 8; Ib++) {
        float acc[4][4] = {};
        for (int Kb = Jb; Kb < Ib; Kb++) {
            load_tile_T(A + (size_t)(Ib * 64) * DN + Kb * 64, DN, sL, tid);
            if (Kb == Jb) {
                for (int u4 = tid; u4 < 1024; u4 += 256) {
                    int k = u4 >> 4, c4 = (u4 & 15) << 2;
                    float4 v = *(const float4*)(Dv + Jb * 4096 + k * 64 + c4);
                    *(float4*)(sW + k * PIT + c4) = v;
                }
            } else {
                int K64 = Kb * 64;
                for (int u = tid; u < 4096; u += 256) {
                    int k = u >> 6, c = u & 63;
                    sW[k * PIT + c] =
                        C[(size_t)(DN - 1 - (K64 + k)) * DN + (DN - 1 - (J64 + c))] * srl[K64 + k];
                }
            }
            __syncthreads();
            gemm64(sL, sW, acc, tx, ty);
            __syncthreads();
        }
        // stage S [m][c] and Dinv_I transposed [m][r]
        #pragma unroll
        for (int a = 0; a < 4; a++)
            *(float4*)(sS + ((ty << 2) + a) * PIT + (tx << 2)) =
                make_float4(acc[a][0], acc[a][1], acc[a][2], acc[a][3]);
        for (int u4 = tid; u4 < 1024; u4 += 256) {
            int r = u4 >> 4, m4 = (u4 & 15) << 2;
            float4 v = *(const float4*)(Dv + Ib * 4096 + r * 64 + m4);
            sD[(m4 + 0) * PIT + r] = v.x; sD[(m4 + 1) * PIT + r] = v.y;
            sD[(m4 + 2) * PIT + r] = v.z; sD[(m4 + 3) * PIT + r] = v.w;
        }
        __syncthreads();
        float wv[4][4] = {};
        gemm64(sD, sS, wv, tx, ty);
        // normalized write: W_IJ = -Dinv_I*S, scaled by dL[row]
        #pragma unroll
        for (int a = 0; a < 4; a++) {
            int r = Ib * 64 + (ty << 2) + a;
            float sc = sdl[r];
            #pragma unroll
            for (int q = 0; q < 4; q++)
                C[(size_t)(DN - 1 - r) * DN + (DN - 1 - (J64 + (tx << 2) + q))] = -wv[a][q] * sc;
        }
        // mirror zero block (strict lower triangle of output)
        {
            int colbase = DN - 64 - Ib * 64;
            for (int u4 = tid; u4 < 1024; u4 += 256) {
                int r = u4 >> 4, c4 = (u4 & 15) << 2;
                *(float4*)(C + (size_t)(DN - 1 - (J64 + r)) * DN + colbase + c4) =
                    make_float4(0.f, 0.f, 0.f, 0.f);
            }
        }
        __syncthreads();
    }
}

// ---------------- 7) mu + logvar from NORMALIZED chol with diag compensation ----------------
__global__ void mu_kernel(const float* __restrict__ cholg, float* __restrict__ mu,
                          float* __restrict__ logvar) {
    int b = blockIdx.x;
    const float* C = cholg + (size_t)b * DN * DN;
    __shared__ float sg[DN], st[DN], sdl[DN], sp[8][DN];
    int tid = threadIdx.x, wrp = tid >> 5, lane = tid & 31;
    for (int i = tid; i < DN; i += 256) {
        sg[i]  = g_gamma[b * DN + (DN - 1 - i)];
        sdl[i] = g_A[(size_t)b * DN * DN + (size_t)i * DN + i];
    }
    for (int j = lane; j < DN; j += 32) sp[wrp][j] = 0.f;
    __syncthreads();
    for (int r = tid; r < DN; r += 256)
        logvar[b * DN + (DN - 1 - r)] = -2.f * logf(sdl[r]);
    // u[r] = (g~[r] + sum_{c<r} C'[r][c] g~[c]) / dL[r]^2
    for (int r = wrp; r < DN; r += 8) {
        float p = 0.f;
        for (int c = lane; c < r; c += 32)
            p += C[(size_t)(DN - 1 - r) * DN + (DN - 1 - c)] * sg[c];
        #pragma unroll
        for (int o = 16; o; o >>= 1) p += __shfl_down_sync(0xffffffffu, p, o);
        if (lane == 0) st[r] = (p + sg[r]) / (sdl[r] * sdl[r]);
    }
    __syncthreads();
    // mu~[c] = u[c] + sum_{r>c} C'[r][c] u[r]
    for (int r = wrp; r < DN; r += 8) {
        float ur = st[r];
        for (int c = lane; c < r; c += 32)
            sp[wrp][c] += C[(size_t)(DN - 1 - r) * DN + (DN - 1 - c)] * ur;
    }
    __syncthreads();
    for (int c = tid; c < DN; c += 256) {
        float s = st[c];
        #pragma unroll
        for (int w = 0; w < 8; w++) s += sp[w][c];
        mu[b * DN + (DN - 1 - c)] = s;
    }
}

// ---------------- launch ----------------
extern "C" void kernel_launch(void* const* d_in, const int* in_sizes, int n_in,
                              void* d_out, int out_size) {
    const float* x     = (const float*)d_in[0];   // [B,T,D]
    const float* w     = (const float*)d_in[1];   // [B,T,1]
    const float* Dw    = (const float*)d_in[2];   // [D]
    const float* cholw = (const float*)d_in[3];   // [D,D]
    float* out    = (float*)d_out;
    float* mu     = out;                          // [B,D]
    float* logvar = out + BN * DN;                // [B,D]
    float* chol   = out + 2 * BN * DN;            // [B,D,D]

    const int SMEM_POTRF = (4160 + 3 * 64 * PIT) * (int)sizeof(float);   // 68864
    const int SMEM_TRINV = (4 * 64 * PIT + 2 * DN) * (int)sizeof(float); // 73728
    cudaFuncSetAttribute((const void*)potrf_kernel,
                         cudaFuncAttributeMaxDynamicSharedMemorySize, SMEM_POTRF);
    cudaFuncSetAttribute((const void*)trinv_main_kernel,
                         cudaFuncAttributeMaxDynamicSharedMemorySize, SMEM_TRINV);

    stats_kernel<<<BN, 512>>>(x, w);
    trinvU_kernel<<<64, 256>>>(cholw, Dw);
    formP_kernel<<<dim3(16, 16), 256>>>();
    initA_kernel<<<dim3(32, BN), 256>>>();
    potrf_kernel<<<BN, 256, SMEM_POTRF>>>();
    trinv_main_kernel<<<dim3(8, BN), 256, SMEM_TRINV>>>(chol);
    mu_kernel<<<BN, 256>>>(chol, mu, logvar);
}